// round 15
// baseline (speedup 1.0000x reference)
#include <cuda_runtime.h>
#include <cstdint>
#include <cstddef>

#define NN 2048
#define EE 32
#define R2F 0.0025f   // float32(0.05^2), matches JAX's weak-typed scalar promotion
#define SPLIT 2       // blocks per source row -> grid 4096 of 512-thread blocks
#define CHUNKS_PER_BLK (64 / SPLIT)   // 32 x 32-dst chunks; adjacent pair per warp
#define CHUNK_BYTES 4096              // 32 dsts x 32 feats x 4B
#define TPB 512                       // 16 warps; same warp granularity as R14

__device__ __forceinline__ uint32_t smem_u32(const void* p) {
    uint32_t a;
    asm("{ .reg .u64 t; cvta.to.shared.u64 t, %1; cvt.u32.u64 %0, t; }"
        : "=r"(a) : "l"(p));
    return a;
}

// Async-proxy bulk store: SMEM zeros -> global. Bypasses the SM store queue.
__device__ __forceinline__ void bulk_store(void* gdst, uint32_t ssrc, int bytes) {
    asm volatile("cp.async.bulk.global.shared::cta.bulk_group [%0], [%1], %2;"
                 :: "l"(gdst), "r"(ssrc), "r"(bytes) : "memory");
}

// Rare path: 2-layer MLP for one valid edge; this lane produces output
// features [4*eb, 4*eb+4). Weights MUST be SMEM-resident: invocation count
// is edge-and-lane amplified (~264K calls); global-path weight loads
// saturate the LSU (measured: +14.5us with __ldg weights in R13).
__device__ __noinline__ float4 edge_mlp(float rx, float ry,
                                        const float4* __restrict__ sW1p,
                                        const float4* __restrict__ sW2,
                                        const float4* __restrict__ sb2,
                                        int eb) {
    float4 acc = sb2[eb];
#pragma unroll 8
    for (int j = 0; j < 32; j++) {
        float4 w1 = sW1p[j];                         // {W1[0][j], W1[1][j], b1[j], 0}
        float h = fmaf(ry, w1.y, fmaf(rx, w1.x, w1.z));
        h = fmaxf(h, 0.0f);
        float4 w2 = sW2[j * 8 + eb];                 // W2[j][4eb .. 4eb+3]
        acc.x = fmaf(h, w2.x, acc.x);
        acc.y = fmaf(h, w2.y, acc.y);
        acc.z = fmaf(h, w2.z, acc.z);
        acc.w = fmaf(h, w2.w, acc.w);
    }
    return acc;
}

// STG fallback for one 32-dst chunk with valid edges.
__device__ __forceinline__ void chunk_with_edges(unsigned mask, float rx, float ry,
                                                 float4* __restrict__ o,
                                                 int lane, int grp, int eb,
                                                 const float4* __restrict__ sW1p,
                                                 const float4* __restrict__ sW2,
                                                 const float4* __restrict__ sb2) {
    const float4 zero4 = make_float4(0.0f, 0.0f, 0.0f, 0.0f);
#pragma unroll 1
    for (int i = 0; i < 8; i++) {
        const unsigned m4 = (mask >> (i * 4)) & 0xFu;   // warp-uniform
        float4 v = zero4;
        if (m4) {
            const int src = i * 4 + grp;
            const float frx = __shfl_sync(0xffffffffu, rx, src);
            const float fry = __shfl_sync(0xffffffffu, ry, src);
            if ((m4 >> grp) & 1u)
                v = edge_mlp(frx, fry, sW1p, sW2, sb2, eb);
        }
        o[i * 32 + lane] = v;                // 512B/warp, coalesced
    }
}

// Grid = 4096 x 512 threads: block b -> source row s = b/SPLIT, half = b%SPLIT.
// 16 warps; warp w owns the ADJACENT chunk pair (2w, 2w+1): contiguous 8KB.
// Same per-warp shape and chip residency as the measured-optimal R14, but
// HALF the per-block fixed costs (prologue, dispatch, drain): 4096 vs 8192.
__global__ void __launch_bounds__(TPB)
graph_edges_kernel(const float* __restrict__ pos,
                   const float* __restrict__ W1,
                   const float* __restrict__ b1,
                   const float* __restrict__ W2,
                   const float* __restrict__ b2,
                   float4* __restrict__ out) {
    __shared__ float4 sW1p[32];            // packed {W1x, W1y, b1, 0}
    __shared__ float4 sW2[256];            // W2[32][32] as 32 rows x 8 float4
    __shared__ float4 sb2[8];
    __shared__ __align__(16) float4 sZero[512];   // 8KB zero tile

    const int tid = threadIdx.x;
    const float4 zero4 = make_float4(0.0f, 0.0f, 0.0f, 0.0f);
    if (tid < 32) sW1p[tid] = make_float4(W1[tid], W1[32 + tid], b1[tid], 0.0f);
    if (tid < 256) sW2[tid] = ((const float4*)W2)[tid];
    if (tid < 8) sb2[tid] = ((const float4*)b2)[tid];
    sZero[tid] = zero4;                    // 512 threads fill 8KB in one shot
    __syncthreads();
    // Order generic-proxy SMEM writes (sZero) before async-proxy bulk reads.
    asm volatile("fence.proxy.async.shared::cta;" ::: "memory");

    const int lane = tid & 31;
    const int warp = tid >> 5;             // 0..15
    const int grp  = lane >> 3;    // which of 4 pairs in a store iteration
    const int eb   = lane & 7;     // which float4 of the 32 features
    const int s    = blockIdx.x / SPLIT;
    const int c0   = (blockIdx.x % SPLIT) * CHUNKS_PER_BLK;

    const uint32_t zaddr = smem_u32(sZero);
    const float2 ps = ((const float2*)pos)[s];

    // This warp's adjacent chunk pair: contiguous 64 dsts.
    const int d0 = (c0 + warp * 2) * 32;
    const float2 pa = ((const float2*)pos)[d0 + lane];
    const float2 pb = ((const float2*)pos)[d0 + 32 + lane];
    const float rx0 = pa.x - ps.x, ry0 = pa.y - ps.y;    // pos[dst]-pos[src]
    const float rx1 = pb.x - ps.x, ry1 = pb.y - ps.y;
    // no-FMA dist2: bit-exact with jnp (mul, mul, add in f32)
    const float d2a = __fadd_rn(__fmul_rn(rx0, rx0), __fmul_rn(ry0, ry0));
    const float d2b = __fadd_rn(__fmul_rn(rx1, rx1), __fmul_rn(ry1, ry1));
    const bool va = (d2a <= R2F) && ((d0 + lane) != s);
    const bool vb = (d2b <= R2F) && ((d0 + 32 + lane) != s);
    const unsigned mask0 = __ballot_sync(0xffffffffu, va);
    const unsigned mask1 = __ballot_sync(0xffffffffu, vb);

    float4* o = out + ((size_t)s * NN + (size_t)d0) * (EE / 4);

    if ((mask0 | mask1) == 0u) {
        // ~60%: one 8KB bulk store covers both chunks.
        if (lane == 0) bulk_store(o, zaddr, 2 * CHUNK_BYTES);
    } else {
        if (mask0 == 0u) {
            if (lane == 0) bulk_store(o, zaddr, CHUNK_BYTES);
        } else {
            chunk_with_edges(mask0, rx0, ry0, o, lane, grp, eb, sW1p, sW2, sb2);
        }
        if (mask1 == 0u) {
            if (lane == 0) bulk_store(o + 256, zaddr, CHUNK_BYTES);
        } else {
            chunk_with_edges(mask1, rx1, ry1, o + 256, lane, grp, eb, sW1p, sW2, sb2);
        }
    }

    // Drain bulk-store group before exit (SMEM source must stay live).
    if (lane == 0) {
        asm volatile("cp.async.bulk.commit_group;" ::: "memory");
        asm volatile("cp.async.bulk.wait_group 0;" ::: "memory");
    }
}

// Inputs (metadata order): node_features (unused), object_positions_2d,
// W1, b1, W2, b2. Output: edge_attr [N, N, E] fp32.
extern "C" void kernel_launch(void* const* d_in, const int* in_sizes, int n_in,
                              void* d_out, int out_size) {
    const float* pos = (const float*)d_in[1];
    const float* W1  = (const float*)d_in[2];
    const float* b1  = (const float*)d_in[3];
    const float* W2  = (const float*)d_in[4];
    const float* b2  = (const float*)d_in[5];
    graph_edges_kernel<<<NN * SPLIT, TPB>>>(pos, W1, b1, W2, b2, (float4*)d_out);
}

// round 17
// speedup vs baseline: 1.0300x; 1.0300x over previous
#include <cuda_runtime.h>
#include <cstdint>
#include <cstddef>

#define NN 2048
#define EE 32
#define R2F 0.0025f   // float32(0.05^2), matches JAX's weak-typed scalar promotion
#define SPLIT 4       // blocks per source row -> grid 8192 (measured optimum)
#define CHUNKS_PER_BLK (64 / SPLIT)   // 16 x 32-dst chunks; adjacent pair per warp
#define CHUNK_BYTES 4096              // 32 dsts x 32 feats x 4B

__device__ __forceinline__ uint32_t smem_u32(const void* p) {
    uint32_t a;
    asm("{ .reg .u64 t; cvta.to.shared.u64 t, %1; cvt.u32.u64 %0, t; }"
        : "=r"(a) : "l"(p));
    return a;
}

// Async-proxy bulk store: SMEM zeros -> global. Bypasses the SM store queue.
// Measured ~2us faster than the equivalent STG.128 stream (R8 -> R9).
__device__ __forceinline__ void bulk_store(void* gdst, uint32_t ssrc, int bytes) {
    asm volatile("cp.async.bulk.global.shared::cta.bulk_group [%0], [%1], %2;"
                 :: "l"(gdst), "r"(ssrc), "r"(bytes) : "memory");
}

// Rare path: 2-layer MLP for one valid edge; this lane produces output
// features [4*eb, 4*eb+4). Weights MUST be SMEM-resident: invocation count
// is edge-and-lane amplified (~264K calls); global-path weight loads
// saturate the LSU (measured: +14.5us with __ldg weights, R13).
__device__ __noinline__ float4 edge_mlp(float rx, float ry,
                                        const float4* __restrict__ sW1p,
                                        const float4* __restrict__ sW2,
                                        const float4* __restrict__ sb2,
                                        int eb) {
    float4 acc = sb2[eb];
#pragma unroll 8
    for (int j = 0; j < 32; j++) {
        float4 w1 = sW1p[j];                         // {W1[0][j], W1[1][j], b1[j], 0}
        float h = fmaf(ry, w1.y, fmaf(rx, w1.x, w1.z));
        h = fmaxf(h, 0.0f);
        float4 w2 = sW2[j * 8 + eb];                 // W2[j][4eb .. 4eb+3]
        acc.x = fmaf(h, w2.x, acc.x);
        acc.y = fmaf(h, w2.y, acc.y);
        acc.z = fmaf(h, w2.z, acc.z);
        acc.w = fmaf(h, w2.w, acc.w);
    }
    return acc;
}

// STG fallback for one 32-dst chunk with valid edges.
__device__ __forceinline__ void chunk_with_edges(unsigned mask, float rx, float ry,
                                                 float4* __restrict__ o,
                                                 int lane, int grp, int eb,
                                                 const float4* __restrict__ sW1p,
                                                 const float4* __restrict__ sW2,
                                                 const float4* __restrict__ sb2) {
    const float4 zero4 = make_float4(0.0f, 0.0f, 0.0f, 0.0f);
#pragma unroll 1
    for (int i = 0; i < 8; i++) {
        const unsigned m4 = (mask >> (i * 4)) & 0xFu;   // warp-uniform
        float4 v = zero4;
        if (m4) {
            const int src = i * 4 + grp;
            const float frx = __shfl_sync(0xffffffffu, rx, src);
            const float fry = __shfl_sync(0xffffffffu, ry, src);
            if ((m4 >> grp) & 1u)
                v = edge_mlp(frx, fry, sW1p, sW2, sb2, eb);
        }
        o[i * 32 + lane] = v;                // 512B/warp, coalesced
    }
}

// FINAL KERNEL (measured optimum across 15 rounds):
// Grid = 8192 x 256: block b -> source row s = b/SPLIT, quarter = b%SPLIT.
// Warp w owns the ADJACENT chunk pair (2w, 2w+1): contiguous 8KB output.
// Both masks zero (~60%) -> ONE 8KB bulk store. Single zero chunk -> 4KB
// bulk store. Valid chunk -> STG path with predicated rare-path MLP.
// 77.8us = ~6.9TB/s effective write (~86% of 8TB/s spec).
__global__ void __launch_bounds__(256)
graph_edges_kernel(const float* __restrict__ pos,
                   const float* __restrict__ W1,
                   const float* __restrict__ b1,
                   const float* __restrict__ W2,
                   const float* __restrict__ b2,
                   float4* __restrict__ out) {
    __shared__ float4 sW1p[32];            // packed {W1x, W1y, b1, 0}
    __shared__ float4 sW2[256];            // W2[32][32] as 32 rows x 8 float4
    __shared__ float4 sb2[8];
    __shared__ __align__(16) float4 sZero[512];   // 8KB zero tile

    const int tid = threadIdx.x;
    const float4 zero4 = make_float4(0.0f, 0.0f, 0.0f, 0.0f);
    if (tid < 32) sW1p[tid] = make_float4(W1[tid], W1[32 + tid], b1[tid], 0.0f);
    sW2[tid] = ((const float4*)W2)[tid];
    if (tid < 8) sb2[tid] = ((const float4*)b2)[tid];
    sZero[tid] = zero4;
    sZero[tid + 256] = zero4;
    __syncthreads();
    // Order generic-proxy SMEM writes (sZero) before async-proxy bulk reads.
    asm volatile("fence.proxy.async.shared::cta;" ::: "memory");

    const int lane = tid & 31;
    const int warp = tid >> 5;
    const int grp  = lane >> 3;    // which of 4 pairs in a store iteration
    const int eb   = lane & 7;     // which float4 of the 32 features
    const int s    = blockIdx.x / SPLIT;
    const int c0   = (blockIdx.x % SPLIT) * CHUNKS_PER_BLK;

    const uint32_t zaddr = smem_u32(sZero);
    const float2 ps = ((const float2*)pos)[s];

    // This warp's adjacent chunk pair: contiguous 64 dsts.
    const int d0 = (c0 + warp * 2) * 32;
    const float2 pa = ((const float2*)pos)[d0 + lane];
    const float2 pb = ((const float2*)pos)[d0 + 32 + lane];
    const float rx0 = pa.x - ps.x, ry0 = pa.y - ps.y;    // pos[dst]-pos[src]
    const float rx1 = pb.x - ps.x, ry1 = pb.y - ps.y;
    // no-FMA dist2: bit-exact with jnp (mul, mul, add in f32)
    const float d2a = __fadd_rn(__fmul_rn(rx0, rx0), __fmul_rn(ry0, ry0));
    const float d2b = __fadd_rn(__fmul_rn(rx1, rx1), __fmul_rn(ry1, ry1));
    const bool va = (d2a <= R2F) && ((d0 + lane) != s);
    const bool vb = (d2b <= R2F) && ((d0 + 32 + lane) != s);
    const unsigned mask0 = __ballot_sync(0xffffffffu, va);
    const unsigned mask1 = __ballot_sync(0xffffffffu, vb);

    float4* o = out + ((size_t)s * NN + (size_t)d0) * (EE / 4);

    if ((mask0 | mask1) == 0u) {
        // ~60%: one 8KB bulk store covers both chunks.
        if (lane == 0) bulk_store(o, zaddr, 2 * CHUNK_BYTES);
    } else {
        if (mask0 == 0u) {
            if (lane == 0) bulk_store(o, zaddr, CHUNK_BYTES);
        } else {
            chunk_with_edges(mask0, rx0, ry0, o, lane, grp, eb, sW1p, sW2, sb2);
        }
        if (mask1 == 0u) {
            if (lane == 0) bulk_store(o + 256, zaddr, CHUNK_BYTES);
        } else {
            chunk_with_edges(mask1, rx1, ry1, o + 256, lane, grp, eb, sW1p, sW2, sb2);
        }
    }

    // Drain bulk-store group before exit (SMEM source must stay live).
    if (lane == 0) {
        asm volatile("cp.async.bulk.commit_group;" ::: "memory");
        asm volatile("cp.async.bulk.wait_group 0;" ::: "memory");
    }
}

// Inputs (metadata order): node_features (unused), object_positions_2d,
// W1, b1, W2, b2. Output: edge_attr [N, N, E] fp32.
extern "C" void kernel_launch(void* const* d_in, const int* in_sizes, int n_in,
                              void* d_out, int out_size) {
    const float* pos = (const float*)d_in[1];
    const float* W1  = (const float*)d_in[2];
    const float* b1  = (const float*)d_in[3];
    const float* W2  = (const float*)d_in[4];
    const float* b2  = (const float*)d_in[5];
    graph_edges_kernel<<<NN * SPLIT, 256>>>(pos, W1, b1, W2, b2, (float4*)d_out);
}